// round 3
// baseline (speedup 1.0000x reference)
#include <cuda_runtime.h>

// Problem constants
#define BB   2
#define LL   2048
#define HH   16
#define DD   64
#define EE   1024
#define MM   (BB * LL)      /* 4096 rows */
#define SATT 68             /* padded smem stride for attention tiles */

// Scratch (device globals — no runtime allocation allowed)
__device__ float g_qkv[(size_t)MM * 3 * EE];   // 48 MB: (B,L,3E)
__device__ float g_att[(size_t)MM * EE];       // 16 MB: (B,L,E)

// ---------------------------------------------------------------------------
// SGEMM (NT): C[M,N] = A[M,K] * W[N,K]^T      A row-major, W row-major [out,in]
// 128x128 tile, BK=8, 256 threads, 8x8 microtile, register prefetch.
// All dims are multiples of tile sizes (M=4096, N in {3072,1024}, K=1024).
// ---------------------------------------------------------------------------
__global__ __launch_bounds__(256, 2)
void sgemm_nt(const float* __restrict__ A, const float* __restrict__ W,
              float* __restrict__ C, int N, int K)
{
    constexpr int BM = 128, BN = 128, BK = 8;
    __shared__ float As[BK][BM];
    __shared__ float Bs[BK][BN];

    const int tid  = threadIdx.x;
    const int tx   = tid & 15;
    const int ty   = tid >> 4;
    const int m0   = blockIdx.y * BM;
    const int n0   = blockIdx.x * BN;
    const int lrow = tid >> 1;          // 0..127
    const int lcol = (tid & 1) * 4;     // 0 or 4

    const float* Ap = A + (size_t)(m0 + lrow) * K + lcol;
    const float* Wp = W + (size_t)(n0 + lrow) * K + lcol;

    float acc[8][8];
#pragma unroll
    for (int i = 0; i < 8; i++)
#pragma unroll
        for (int j = 0; j < 8; j++) acc[i][j] = 0.f;

    float4 av = *(const float4*)Ap;
    float4 bv = *(const float4*)Wp;

    for (int k0 = 0; k0 < K; k0 += BK) {
        __syncthreads();   // previous iteration's compute done
        As[lcol + 0][lrow] = av.x;
        As[lcol + 1][lrow] = av.y;
        As[lcol + 2][lrow] = av.z;
        As[lcol + 3][lrow] = av.w;
        Bs[lcol + 0][lrow] = bv.x;
        Bs[lcol + 1][lrow] = bv.y;
        Bs[lcol + 2][lrow] = bv.z;
        Bs[lcol + 3][lrow] = bv.w;
        __syncthreads();

        if (k0 + BK < K) {            // prefetch next tile during compute
            av = *(const float4*)(Ap + k0 + BK);
            bv = *(const float4*)(Wp + k0 + BK);
        }

#pragma unroll
        for (int k = 0; k < BK; k++) {
            float a[8], b[8];
            *(float4*)&a[0] = *(const float4*)&As[k][ty * 8];
            *(float4*)&a[4] = *(const float4*)&As[k][ty * 8 + 4];
            *(float4*)&b[0] = *(const float4*)&Bs[k][tx * 8];
            *(float4*)&b[4] = *(const float4*)&Bs[k][tx * 8 + 4];
#pragma unroll
            for (int i = 0; i < 8; i++)
#pragma unroll
                for (int j = 0; j < 8; j++)
                    acc[i][j] += a[i] * b[j];
        }
    }

#pragma unroll
    for (int i = 0; i < 8; i++) {
        float* Cp = C + (size_t)(m0 + ty * 8 + i) * N + n0 + tx * 8;
        *(float4*)Cp       = make_float4(acc[i][0], acc[i][1], acc[i][2], acc[i][3]);
        *(float4*)(Cp + 4) = make_float4(acc[i][4], acc[i][5], acc[i][6], acc[i][7]);
    }
}

// ---------------------------------------------------------------------------
// Flash attention, fp32, causal. One CTA = 64 queries of one (b,h).
// qkv layout: (B, L, 3E); q at col h*64+d, k at E+h*64+d, v at 2E+h*64+d.
// Smem: Qt[d][q], Kt[d][c] (d-major for contiguous GEMM reads), Vs[c][d], Ss[q][c].
// Thread maps: S-GEMM 16x16 grid of 4x4 microtiles; softmax/PV: 4 threads/row,
// 16 output dims each (quad shfl reductions, V reads quad-broadcast).
// ---------------------------------------------------------------------------
__global__ __launch_bounds__(256, 2)
void attn_fp32(const float* __restrict__ qkv, float* __restrict__ out)
{
    extern __shared__ float sm[];
    float* Qt = sm;                    // [64][SATT]
    float* Kt = sm + 64 * SATT;        // [64][SATT]
    float* Vs = sm + 2 * 64 * SATT;    // [64][SATT]
    float* Ss = sm + 3 * 64 * SATT;    // [64][SATT]

    const int tid = threadIdx.x;
    const int qb  = (int)gridDim.x - 1 - (int)blockIdx.x;  // big tiles first
    const int h   = blockIdx.y;
    const int b   = blockIdx.z;
    const int row = tid >> 2;        // 0..63
    const int cg  = tid & 3;
    const int c0  = cg * 16;
    const int ty  = tid >> 4;        // S-GEMM mapping
    const int tx  = tid & 15;

    const float* base = qkv + (size_t)b * LL * 3 * EE + (size_t)h * DD;

    // Load Q transposed, pre-scaled by 1/sqrt(D)=0.125 (exact power of two)
    {
        const float* qrow = base + (size_t)(qb * 64 + row) * (3 * EE) + c0;
#pragma unroll
        for (int j = 0; j < 16; j += 4) {
            float4 v = *(const float4*)(qrow + j);
            Qt[(c0 + j + 0) * SATT + row] = v.x * 0.125f;
            Qt[(c0 + j + 1) * SATT + row] = v.y * 0.125f;
            Qt[(c0 + j + 2) * SATT + row] = v.z * 0.125f;
            Qt[(c0 + j + 3) * SATT + row] = v.w * 0.125f;
        }
    }

    float m_i = -1e30f, l_i = 0.f;
    float O[16];
#pragma unroll
    for (int j = 0; j < 16; j++) O[j] = 0.f;

    for (int kb = 0; kb <= qb; kb++) {
        __syncthreads();   // previous PV done reading Kt/Vs
        {
            const float* krow = base + (size_t)(kb * 64 + row) * (3 * EE) + EE + c0;
#pragma unroll
            for (int j = 0; j < 16; j += 4) {
                float4 v = *(const float4*)(krow + j);
                Kt[(c0 + j + 0) * SATT + row] = v.x;
                Kt[(c0 + j + 1) * SATT + row] = v.y;
                Kt[(c0 + j + 2) * SATT + row] = v.z;
                Kt[(c0 + j + 3) * SATT + row] = v.w;
            }
            const float* vrow = base + (size_t)(kb * 64 + row) * (3 * EE) + 2 * EE + c0;
#pragma unroll
            for (int j = 0; j < 16; j += 4)
                *(float4*)&Vs[row * SATT + c0 + j] = *(const float4*)(vrow + j);
        }
        __syncthreads();

        // S = (Q/8) K^T : 4x4 microtile per thread
        float s[4][4];
#pragma unroll
        for (int i = 0; i < 4; i++)
#pragma unroll
            for (int j = 0; j < 4; j++) s[i][j] = 0.f;

#pragma unroll 16
        for (int k = 0; k < 64; k++) {
            float4 aa = *(const float4*)&Qt[k * SATT + ty * 4];
            float4 bb = *(const float4*)&Kt[k * SATT + tx * 4];
            float a[4]  = {aa.x, aa.y, aa.z, aa.w};
            float bbv[4] = {bb.x, bb.y, bb.z, bb.w};
#pragma unroll
            for (int i = 0; i < 4; i++)
#pragma unroll
                for (int j = 0; j < 4; j++)
                    s[i][j] += a[i] * bbv[j];
        }
#pragma unroll
        for (int i = 0; i < 4; i++)
            *(float4*)&Ss[(ty * 4 + i) * SATT + tx * 4] =
                make_float4(s[i][0], s[i][1], s[i][2], s[i][3]);
        __syncthreads();

        // Online softmax: row = tid>>2, this thread owns 16 cols (c0..c0+15)
        float p[16];
#pragma unroll
        for (int j = 0; j < 16; j += 4) {
            float4 v = *(const float4*)&Ss[row * SATT + c0 + j];
            p[j] = v.x; p[j + 1] = v.y; p[j + 2] = v.z; p[j + 3] = v.w;
        }
        if (kb == qb) {
#pragma unroll
            for (int j = 0; j < 16; j++)
                if (c0 + j > row) p[j] = -1e30f;   // causal mask on diag block
        }
        float mloc = p[0];
#pragma unroll
        for (int j = 1; j < 16; j++) mloc = fmaxf(mloc, p[j]);
        mloc = fmaxf(mloc, __shfl_xor_sync(0xffffffffu, mloc, 1));
        mloc = fmaxf(mloc, __shfl_xor_sync(0xffffffffu, mloc, 2));
        float m_new = fmaxf(m_i, mloc);
        float corr  = __expf(m_i - m_new);
        float lsum = 0.f;
#pragma unroll
        for (int j = 0; j < 16; j++) { p[j] = __expf(p[j] - m_new); lsum += p[j]; }
        lsum += __shfl_xor_sync(0xffffffffu, lsum, 1);
        lsum += __shfl_xor_sync(0xffffffffu, lsum, 2);
        l_i = l_i * corr + lsum;
        m_i = m_new;
#pragma unroll
        for (int j = 0; j < 16; j++) O[j] *= corr;
#pragma unroll
        for (int j = 0; j < 16; j += 4)
            *(float4*)&Ss[row * SATT + c0 + j] =
                make_float4(p[j], p[j + 1], p[j + 2], p[j + 3]);
        __syncthreads();

        // O += P @ V  (p scalar broadcast within quad; V rows broadcast too)
#pragma unroll 4
        for (int k = 0; k < 64; k += 4) {
            float4 pv = *(const float4*)&Ss[row * SATT + k];
            float pk[4] = {pv.x, pv.y, pv.z, pv.w};
#pragma unroll
            for (int kk = 0; kk < 4; kk++) {
#pragma unroll
                for (int j = 0; j < 16; j += 4) {
                    float4 vv = *(const float4*)&Vs[(k + kk) * SATT + c0 + j];
                    O[j + 0] += pk[kk] * vv.x;
                    O[j + 1] += pk[kk] * vv.y;
                    O[j + 2] += pk[kk] * vv.z;
                    O[j + 3] += pk[kk] * vv.w;
                }
            }
        }
    }

    const float inv = 1.f / l_i;
    float* orow = out + (size_t)(b * LL + qb * 64 + row) * EE + h * DD + c0;
#pragma unroll
    for (int j = 0; j < 16; j += 4)
        *(float4*)(orow + j) =
            make_float4(O[j] * inv, O[j + 1] * inv, O[j + 2] * inv, O[j + 3] * inv);
}

// ---------------------------------------------------------------------------
extern "C" void kernel_launch(void* const* d_in, const int* in_sizes, int n_in,
                              void* d_out, int out_size)
{
    (void)in_sizes; (void)n_in; (void)out_size;
    const float* net_in = (const float*)d_in[0];   // (B,L,E)
    const float* W_qkv  = (const float*)d_in[1];   // (3E,E)
    const float* W_out  = (const float*)d_in[2];   // (E,E)
    float* outp = (float*)d_out;                   // (B,L,E)

    float* qkv_ptr = nullptr;
    float* att_ptr = nullptr;
    cudaGetSymbolAddress((void**)&qkv_ptr, g_qkv);
    cudaGetSymbolAddress((void**)&att_ptr, g_att);

    const int attn_smem = 4 * 64 * SATT * (int)sizeof(float);   // 69632 B
    cudaFuncSetAttribute(attn_fp32,
                         cudaFuncAttributeMaxDynamicSharedMemorySize, attn_smem);

    // 1) QKV projection: (B*L, 3E) = net_in @ W_qkv^T
    dim3 g1((3 * EE) / 128, MM / 128);
    sgemm_nt<<<g1, 256>>>(net_in, W_qkv, qkv_ptr, 3 * EE, EE);

    // 2) Causal flash attention -> g_att (B,L,E)
    dim3 ga(LL / 64, HH, BB);
    attn_fp32<<<ga, 256, attn_smem>>>(qkv_ptr, att_ptr);

    // 3) Output projection: d_out = g_att @ W_out^T
    dim3 g3(EE / 128, MM / 128);
    sgemm_nt<<<g3, 256>>>(att_ptr, W_out, outp, EE, EE);
}

// round 4
// speedup vs baseline: 1.6108x; 1.6108x over previous
#include <cuda_runtime.h>

// Problem constants
#define BB   2
#define LL   2048
#define HH   16
#define DD   64
#define EE   1024
#define MM   (BB * LL)      /* 4096 rows */

// Attention tiling
#define QB   128            /* queries per CTA */
#define KVB  64             /* keys per inner block */
#define QSTR 132            /* Qt stride (pad, /4-aligned) */
#define KSTR 68             /* Kt/Vs/Ss stride (pad) */

// Scratch (device globals — no runtime allocation allowed)
__device__ float g_qkv[(size_t)MM * 3 * EE];   // 48 MB: (B,L,3E)
__device__ float g_att[(size_t)MM * EE];       // 16 MB: (B,L,E)

// ---------------------------------------------------------------------------
// SGEMM (NT): C[M,N] = A[M,K] * W[N,K]^T.  128x128 tile, BK=8, 256 threads,
// 8x8 microtile. Double-buffered smem: ONE barrier per K-block, global
// prefetch fully overlapped with compute.
// ---------------------------------------------------------------------------
__global__ __launch_bounds__(256, 2)
void sgemm_nt(const float* __restrict__ A, const float* __restrict__ W,
              float* __restrict__ C, int N, int K)
{
    constexpr int BM = 128, BN = 128, BK = 8;
    __shared__ float As[2][BK][BM];
    __shared__ float Bs[2][BK][BN];

    const int tid  = threadIdx.x;
    const int tx   = tid & 15;
    const int ty   = tid >> 4;
    const int m0   = blockIdx.y * BM;
    const int n0   = blockIdx.x * BN;
    const int lrow = tid >> 1;          // 0..127
    const int lcol = (tid & 1) * 4;     // 0 or 4

    const float* Ap = A + (size_t)(m0 + lrow) * K + lcol;
    const float* Wp = W + (size_t)(n0 + lrow) * K + lcol;

    float acc[8][8];
#pragma unroll
    for (int i = 0; i < 8; i++)
#pragma unroll
        for (int j = 0; j < 8; j++) acc[i][j] = 0.f;

    // Fill buffer 0
    {
        float4 av = *(const float4*)Ap;
        float4 bv = *(const float4*)Wp;
        As[0][lcol + 0][lrow] = av.x;
        As[0][lcol + 1][lrow] = av.y;
        As[0][lcol + 2][lrow] = av.z;
        As[0][lcol + 3][lrow] = av.w;
        Bs[0][lcol + 0][lrow] = bv.x;
        Bs[0][lcol + 1][lrow] = bv.y;
        Bs[0][lcol + 2][lrow] = bv.z;
        Bs[0][lcol + 3][lrow] = bv.w;
    }
    __syncthreads();

    int buf = 0;
    for (int k0 = 0; k0 < K; k0 += BK) {
        const bool has_next = (k0 + BK < K);
        float4 av, bv;
        if (has_next) {                    // prefetch next tile (overlaps compute)
            av = *(const float4*)(Ap + k0 + BK);
            bv = *(const float4*)(Wp + k0 + BK);
        }

#pragma unroll
        for (int k = 0; k < BK; k++) {
            float a[8], b[8];
            *(float4*)&a[0] = *(const float4*)&As[buf][k][ty * 8];
            *(float4*)&a[4] = *(const float4*)&As[buf][k][ty * 8 + 4];
            *(float4*)&b[0] = *(const float4*)&Bs[buf][k][tx * 8];
            *(float4*)&b[4] = *(const float4*)&Bs[buf][k][tx * 8 + 4];
#pragma unroll
            for (int i = 0; i < 8; i++)
#pragma unroll
                for (int j = 0; j < 8; j++)
                    acc[i][j] += a[i] * b[j];
        }

        if (has_next) {
            const int nb = buf ^ 1;        // write OTHER buffer: no WAR on cur
            As[nb][lcol + 0][lrow] = av.x;
            As[nb][lcol + 1][lrow] = av.y;
            As[nb][lcol + 2][lrow] = av.z;
            As[nb][lcol + 3][lrow] = av.w;
            Bs[nb][lcol + 0][lrow] = bv.x;
            Bs[nb][lcol + 1][lrow] = bv.y;
            Bs[nb][lcol + 2][lrow] = bv.z;
            Bs[nb][lcol + 3][lrow] = bv.w;
            __syncthreads();               // single barrier per block
            buf = nb;
        }
    }

#pragma unroll
    for (int i = 0; i < 8; i++) {
        float* Cp = C + (size_t)(m0 + ty * 8 + i) * N + n0 + tx * 8;
        *(float4*)Cp       = make_float4(acc[i][0], acc[i][1], acc[i][2], acc[i][3]);
        *(float4*)(Cp + 4) = make_float4(acc[i][4], acc[i][5], acc[i][6], acc[i][7]);
    }
}

// ---------------------------------------------------------------------------
// Flash attention v2, fp32, causal. One CTA = 128 queries of one (b,h),
// 64-key inner blocks. 256 threads.
//   S-GEMM:  thread (ty,tx) = 8q x 4k microtile  (1.5 B smem / FMA)
//   softmax: thread pair (tid>>1) owns one row, 32 keys each half
//   PV:      thread (ty,tx) = 8q x 4d microtile, O in registers across blocks
// Row state (corr, 1/l) crosses thread mappings via tiny smem arrays.
// Smem 104448 B -> 2 CTAs/SM.
// ---------------------------------------------------------------------------
__global__ __launch_bounds__(256, 2)
void attn_fp32(const float* __restrict__ qkv, float* __restrict__ out)
{
    extern __shared__ float sm[];
    float* Qt  = sm;                      // [64][QSTR]  (d-major)
    float* Kt  = Qt + 64 * QSTR;          // [64][KSTR]  (d-major)
    float* Vs  = Kt + 64 * KSTR;          // [64][KSTR]  (k-major)
    float* Ss  = Vs + 64 * KSTR;          // [QB][KSTR]
    float* cor = Ss + QB * KSTR;          // [QB]
    float* liv = cor + QB;                // [QB]

    const int tid = threadIdx.x;
    const int qb  = (int)gridDim.x - 1 - (int)blockIdx.x;  // big tiles first
    const int h   = blockIdx.y;
    const int b   = blockIdx.z;

    const int ty = tid >> 4;              // 0..15  -> q0 = ty*8
    const int tx = tid & 15;              // 0..15  -> k/d quad = tx*4
    const int q0 = ty * 8;
    const int x4 = tx * 4;
    const int row2 = tid >> 1;            // softmax row 0..127
    const int ch   = (tid & 1) * 32;      // softmax col half

    const float* base = qkv + (size_t)b * LL * 3 * EE + (size_t)h * DD;

    // Load Q transposed (d-major), pre-scaled by 1/sqrt(D)=0.125 (exact)
    {
        const int r  = tid >> 1;
        const int c0 = (tid & 1) * 32;
        const float* qrow = base + (size_t)(qb * QB + r) * (3 * EE) + c0;
#pragma unroll
        for (int j = 0; j < 32; j += 4) {
            float4 v = *(const float4*)(qrow + j);
            Qt[(c0 + j + 0) * QSTR + r] = v.x * 0.125f;
            Qt[(c0 + j + 1) * QSTR + r] = v.y * 0.125f;
            Qt[(c0 + j + 2) * QSTR + r] = v.z * 0.125f;
            Qt[(c0 + j + 3) * QSTR + r] = v.w * 0.125f;
        }
    }

    float m_i = -1e30f, l_i = 0.f;
    float O[8][4];
#pragma unroll
    for (int i = 0; i < 8; i++)
#pragma unroll
        for (int j = 0; j < 4; j++) O[i][j] = 0.f;

    const int nkb = 2 * qb + 2;
    for (int kb = 0; kb < nkb; kb++) {
        __syncthreads();   // prev PV done with Kt/Vs/Ss
        {
            const int r  = tid >> 2;               // 0..63
            const int c0 = (tid & 3) * 16;
            const float* krow = base + (size_t)(kb * KVB + r) * (3 * EE) + EE + c0;
#pragma unroll
            for (int j = 0; j < 16; j += 4) {
                float4 v = *(const float4*)(krow + j);
                Kt[(c0 + j + 0) * KSTR + r] = v.x;
                Kt[(c0 + j + 1) * KSTR + r] = v.y;
                Kt[(c0 + j + 2) * KSTR + r] = v.z;
                Kt[(c0 + j + 3) * KSTR + r] = v.w;
            }
            const float* vrow = base + (size_t)(kb * KVB + r) * (3 * EE) + 2 * EE + c0;
#pragma unroll
            for (int j = 0; j < 16; j += 4)
                *(float4*)&Vs[r * KSTR + c0 + j] = *(const float4*)(vrow + j);
        }
        __syncthreads();

        // ---- S = (Q/8) K^T : 8x4 microtile ----
        float s[8][4];
#pragma unroll
        for (int i = 0; i < 8; i++)
#pragma unroll
            for (int j = 0; j < 4; j++) s[i][j] = 0.f;

#pragma unroll 8
        for (int d = 0; d < DD; d++) {
            float a[8], bb[4];
            *(float4*)&a[0]  = *(const float4*)&Qt[d * QSTR + q0];
            *(float4*)&a[4]  = *(const float4*)&Qt[d * QSTR + q0 + 4];
            *(float4*)&bb[0] = *(const float4*)&Kt[d * KSTR + x4];
#pragma unroll
            for (int i = 0; i < 8; i++)
#pragma unroll
                for (int j = 0; j < 4; j++)
                    s[i][j] += a[i] * bb[j];
        }
#pragma unroll
        for (int i = 0; i < 8; i++)
            *(float4*)&Ss[(q0 + i) * KSTR + x4] =
                make_float4(s[i][0], s[i][1], s[i][2], s[i][3]);
        __syncthreads();

        // ---- online softmax (2 threads per row, 32 keys each) ----
        {
            float p[32];
#pragma unroll
            for (int j = 0; j < 32; j += 4) {
                float4 v = *(const float4*)&Ss[row2 * KSTR + ch + j];
                p[j] = v.x; p[j + 1] = v.y; p[j + 2] = v.z; p[j + 3] = v.w;
            }
            if (kb >= 2 * qb) {                    // partial (diagonal) blocks
                const int gq  = qb * QB + row2;
                const int k0g = kb * KVB + ch;
#pragma unroll
                for (int j = 0; j < 32; j++)
                    if (k0g + j > gq) p[j] = -1e30f;
            }
            float mloc = p[0];
#pragma unroll
            for (int j = 1; j < 32; j++) mloc = fmaxf(mloc, p[j]);
            mloc = fmaxf(mloc, __shfl_xor_sync(0xffffffffu, mloc, 1));
            const float m_new = fmaxf(m_i, mloc);
            const float c     = __expf(m_i - m_new);
            float ls = 0.f;
#pragma unroll
            for (int j = 0; j < 32; j++) { p[j] = __expf(p[j] - m_new); ls += p[j]; }
            ls += __shfl_xor_sync(0xffffffffu, ls, 1);
            l_i = l_i * c + ls;
            m_i = m_new;
            if ((tid & 1) == 0) cor[row2] = c;
#pragma unroll
            for (int j = 0; j < 32; j += 4)
                *(float4*)&Ss[row2 * KSTR + ch + j] =
                    make_float4(p[j], p[j + 1], p[j + 2], p[j + 3]);
        }
        __syncthreads();

        // ---- O = O*corr + P @ V : 8q x 4d per thread ----
#pragma unroll
        for (int i = 0; i < 8; i++) {
            const float c = cor[q0 + i];
            O[i][0] *= c; O[i][1] *= c; O[i][2] *= c; O[i][3] *= c;
        }
#pragma unroll 2
        for (int k4 = 0; k4 < KVB; k4 += 4) {
            float4 v0 = *(const float4*)&Vs[(k4 + 0) * KSTR + x4];
            float4 v1 = *(const float4*)&Vs[(k4 + 1) * KSTR + x4];
            float4 v2 = *(const float4*)&Vs[(k4 + 2) * KSTR + x4];
            float4 v3 = *(const float4*)&Vs[(k4 + 3) * KSTR + x4];
#pragma unroll
            for (int half = 0; half < 2; half++) {
#pragma unroll
                for (int i = 0; i < 4; i++) {
                    const int r = half * 4 + i;
                    float4 pv = *(const float4*)&Ss[(q0 + r) * KSTR + k4];
                    O[r][0] = fmaf(pv.x, v0.x, O[r][0]);
                    O[r][1] = fmaf(pv.x, v0.y, O[r][1]);
                    O[r][2] = fmaf(pv.x, v0.z, O[r][2]);
                    O[r][3] = fmaf(pv.x, v0.w, O[r][3]);
                    O[r][0] = fmaf(pv.y, v1.x, O[r][0]);
                    O[r][1] = fmaf(pv.y, v1.y, O[r][1]);
                    O[r][2] = fmaf(pv.y, v1.z, O[r][2]);
                    O[r][3] = fmaf(pv.y, v1.w, O[r][3]);
                    O[r][0] = fmaf(pv.z, v2.x, O[r][0]);
                    O[r][1] = fmaf(pv.z, v2.y, O[r][1]);
                    O[r][2] = fmaf(pv.z, v2.z, O[r][2]);
                    O[r][3] = fmaf(pv.z, v2.w, O[r][3]);
                    O[r][0] = fmaf(pv.w, v3.x, O[r][0]);
                    O[r][1] = fmaf(pv.w, v3.y, O[r][1]);
                    O[r][2] = fmaf(pv.w, v3.z, O[r][2]);
                    O[r][3] = fmaf(pv.w, v3.w, O[r][3]);
                }
            }
        }
    }

    // epilogue: publish 1/l from row owners, scale + store
    if ((tid & 1) == 0) liv[row2] = 1.f / l_i;
    __syncthreads();
#pragma unroll
    for (int i = 0; i < 8; i++) {
        const float inv = liv[q0 + i];
        float* orow = out + (size_t)(b * LL + qb * QB + q0 + i) * EE + h * DD + x4;
        *(float4*)orow = make_float4(O[i][0] * inv, O[i][1] * inv,
                                     O[i][2] * inv, O[i][3] * inv);
    }
}

// ---------------------------------------------------------------------------
extern "C" void kernel_launch(void* const* d_in, const int* in_sizes, int n_in,
                              void* d_out, int out_size)
{
    (void)in_sizes; (void)n_in; (void)out_size;
    const float* net_in = (const float*)d_in[0];   // (B,L,E)
    const float* W_qkv  = (const float*)d_in[1];   // (3E,E)
    const float* W_out  = (const float*)d_in[2];   // (E,E)
    float* outp = (float*)d_out;                   // (B,L,E)

    float* qkv_ptr = nullptr;
    float* att_ptr = nullptr;
    cudaGetSymbolAddress((void**)&qkv_ptr, g_qkv);
    cudaGetSymbolAddress((void**)&att_ptr, g_att);

    const int attn_smem = (64 * QSTR + 2 * 64 * KSTR + QB * KSTR + 2 * QB)
                          * (int)sizeof(float);    // 104448 B
    cudaFuncSetAttribute(attn_fp32,
                         cudaFuncAttributeMaxDynamicSharedMemorySize, attn_smem);

    // 1) QKV projection: (B*L, 3E) = net_in @ W_qkv^T
    dim3 g1((3 * EE) / 128, MM / 128);
    sgemm_nt<<<g1, 256>>>(net_in, W_qkv, qkv_ptr, 3 * EE, EE);

    // 2) Causal flash attention -> g_att (B,L,E)
    dim3 ga(LL / QB, HH, BB);
    attn_fp32<<<ga, 256, attn_smem>>>(qkv_ptr, att_ptr);

    // 3) Output projection: d_out = g_att @ W_out^T
    dim3 g3(EE / 128, MM / 128);
    sgemm_nt<<<g3, 256>>>(att_ptr, W_out, outp, EE, EE);
}

// round 7
// speedup vs baseline: 1.9728x; 1.2247x over previous
#include <cuda_runtime.h>
#include <cuda_bf16.h>
#include <cstdint>

// Problem constants
#define BB   2
#define LL   2048
#define HH   16
#define DD   64
#define EE   1024
#define MM   (BB * LL)      /* 4096 rows */

// Attention tiling
#define QB   128
#define KVB  64
#define QSTR 132
#define KSTR 68

// GEMM smem geometry: K-chunk = 64 bf16 = 128 B/row, padded to 144 B
#define GROWB   144
#define GTILEB  (128 * GROWB)          /* 18432 B per operand tile */
#define GBUFB   (2 * GTILEB)           /* A+B one stage */
#define GSMEM   (2 * GBUFB)            /* double buffered = 73728 B */

// ---------------------------------------------------------------------------
// Scratch (device globals — no runtime allocation allowed)
// ---------------------------------------------------------------------------
__device__ float g_qkv[(size_t)MM * 3 * EE];            // 48 MB  (B,L,3E) fp32
__device__ float g_att[(size_t)MM * EE];                // 16 MB  (B,L,E)  fp32
__device__ __nv_bfloat16 g_xhi[(size_t)MM * EE];
__device__ __nv_bfloat16 g_xlo[(size_t)MM * EE];
__device__ __nv_bfloat16 g_wqhi[(size_t)3 * EE * EE];
__device__ __nv_bfloat16 g_wqlo[(size_t)3 * EE * EE];
__device__ __nv_bfloat16 g_wohi[(size_t)EE * EE];
__device__ __nv_bfloat16 g_wolo[(size_t)EE * EE];
__device__ __nv_bfloat16 g_ahi[(size_t)MM * EE];
__device__ __nv_bfloat16 g_alo[(size_t)MM * EE];

// ---------------------------------------------------------------------------
// PTX helpers (baseline ISA only — no arch-specific 'a' features)
// ---------------------------------------------------------------------------
__device__ __forceinline__ uint32_t smem_u32(const void* p) {
    uint32_t a;
    asm("{ .reg .u64 t; cvta.to.shared.u64 t, %1; cvt.u32.u64 %0, t; }"
        : "=r"(a) : "l"(p));
    return a;
}
__device__ __forceinline__ void cp16(uint32_t saddr, const void* gaddr) {
    asm volatile("cp.async.cg.shared.global [%0], [%1], 16;"
                 :: "r"(saddr), "l"(gaddr) : "memory");
}
__device__ __forceinline__ void cp_commit() {
    asm volatile("cp.async.commit_group;" ::: "memory");
}
__device__ __forceinline__ void cp_wait1() {
    asm volatile("cp.async.wait_group 1;" ::: "memory");
}
__device__ __forceinline__ void cp_wait0() {
    asm volatile("cp.async.wait_group 0;" ::: "memory");
}
__device__ __forceinline__ void ldm_x4(uint32_t addr, uint32_t& r0, uint32_t& r1,
                                       uint32_t& r2, uint32_t& r3) {
    asm volatile("ldmatrix.sync.aligned.m8n8.x4.shared.b16 {%0,%1,%2,%3}, [%4];"
                 : "=r"(r0), "=r"(r1), "=r"(r2), "=r"(r3) : "r"(addr));
}
__device__ __forceinline__ void mma_bf16(float* c, const uint32_t* a,
                                         uint32_t b0, uint32_t b1) {
    asm volatile(
        "mma.sync.aligned.m16n8k16.row.col.f32.bf16.bf16.f32 "
        "{%0,%1,%2,%3}, {%4,%5,%6,%7}, {%8,%9}, {%0,%1,%2,%3};"
        : "+f"(c[0]), "+f"(c[1]), "+f"(c[2]), "+f"(c[3])
        : "r"(a[0]), "r"(a[1]), "r"(a[2]), "r"(a[3]), "r"(b0), "r"(b1));
}

// ---------------------------------------------------------------------------
// fp32 -> (hi, lo) bf16 split, vectorized
// ---------------------------------------------------------------------------
__global__ void split_fp32(const float* __restrict__ x, __nv_bfloat16* __restrict__ hi,
                           __nv_bfloat16* __restrict__ lo, int n4)
{
    int i = blockIdx.x * blockDim.x + threadIdx.x;
    if (i >= n4) return;
    float4 v = ((const float4*)x)[i];
    float f[4] = {v.x, v.y, v.z, v.w};
    uint32_t hb[4], lb[4];
#pragma unroll
    for (int j = 0; j < 4; ++j) {
        __nv_bfloat16 h = __float2bfloat16(f[j]);
        float r = f[j] - __bfloat162float(h);
        __nv_bfloat16 l = __float2bfloat16(r);
        hb[j] = (uint32_t)__bfloat16_as_ushort(h);
        lb[j] = (uint32_t)__bfloat16_as_ushort(l);
    }
    ((uint2*)hi)[i] = make_uint2(hb[0] | (hb[1] << 16), hb[2] | (hb[3] << 16));
    ((uint2*)lo)[i] = make_uint2(lb[0] | (lb[1] << 16), lb[2] | (lb[3] << 16));
}

// ---------------------------------------------------------------------------
// mma.sync bf16 3-way-split GEMM:  C[M,N] = A[M,K]*B[N,K]^T  (fp32-equivalent)
// Logical K' = 3*1024: phases (Ahi,Bhi), (Alo,Bhi), (Ahi,Blo).
// 128x128 CTA tile, 8 warps (2m x 4n), warp tile 64x32 = 4x4 m16n8k16.
// K-chunks of 64 bf16, cp.async double-buffered pipeline.
// ---------------------------------------------------------------------------
__global__ __launch_bounds__(256, 2)
void gemm3x(const __nv_bfloat16* __restrict__ Ahi, const __nv_bfloat16* __restrict__ Alo,
            const __nv_bfloat16* __restrict__ Bhi, const __nv_bfloat16* __restrict__ Blo,
            float* __restrict__ C, int N)
{
    extern __shared__ __align__(16) char smraw[];
    const uint32_t sbase = smem_u32(smraw);

    const int tid  = threadIdx.x;
    const int wid  = tid >> 5;
    const int lane = tid & 31;
    const int m0   = blockIdx.y * 128;
    const int n0   = blockIdx.x * 128;

    // loader mapping: row r = tid>>1 (0..127), half h = tid&1 (64 B each)
    const int lr = tid >> 1;
    const int lh = tid & 1;
    const uint32_t sArow = sbase + (uint32_t)(lr * GROWB + lh * 64);
    const uint32_t sBrow = sArow + GTILEB;
    const size_t gAoff = (size_t)(m0 + lr) * EE + lh * 32;
    const size_t gBoff = (size_t)(n0 + lr) * EE + lh * 32;

    // warp compute mapping
    const int wm = wid & 1;          // 0..1 -> m base wm*64
    const int wn = wid >> 1;         // 0..3 -> n base wn*32
    uint32_t aoff[4], boff[2];
#pragma unroll
    for (int i = 0; i < 4; ++i)
        aoff[i] = (uint32_t)((wm * 64 + i * 16 + (lane & 15)) * GROWB + (lane >> 4) * 16);
#pragma unroll
    for (int jp = 0; jp < 2; ++jp)
        boff[jp] = (uint32_t)(GTILEB + (wn * 32 + jp * 16 + (lane & 15)) * GROWB
                              + (lane >> 4) * 16);

    float acc[4][4][4];
#pragma unroll
    for (int i = 0; i < 4; ++i)
#pragma unroll
        for (int j = 0; j < 4; ++j)
#pragma unroll
            for (int v = 0; v < 4; ++v) acc[i][j][v] = 0.f;

    // prologue: issue chunk 0 = (Ahi, Bhi) k0=0 into buffer 0
    {
        const __nv_bfloat16* ga = Ahi + gAoff;
        const __nv_bfloat16* gb = Bhi + gBoff;
#pragma unroll
        for (int q = 0; q < 4; ++q) {
            cp16(sArow + q * 16, ga + q * 8);
            cp16(sBrow + q * 16, gb + q * 8);
        }
        cp_commit();
    }

    int buf = 0;
    for (int c = 0; c < 48; ++c) {
        const bool more = (c + 1 < 48);
        if (more) {                          // issue chunk c+1 into other buffer
            const int cn = c + 1;
            const int ph = cn >> 4;
            const int k0 = (cn & 15) * 64;
            const __nv_bfloat16* ga = ((ph == 1) ? Alo : Ahi) + gAoff + k0;
            const __nv_bfloat16* gb = ((ph == 2) ? Blo : Bhi) + gBoff + k0;
            const uint32_t so = (uint32_t)((buf ^ 1) * GBUFB);
#pragma unroll
            for (int q = 0; q < 4; ++q) {
                cp16(sArow + so + q * 16, ga + q * 8);
                cp16(sBrow + so + q * 16, gb + q * 8);
            }
            cp_commit();
            cp_wait1();                      // chunk c complete (1 group pending)
        } else {
            cp_wait0();
        }
        __syncthreads();                     // chunk c visible to all

        const uint32_t sb = sbase + (uint32_t)(buf * GBUFB);
#pragma unroll
        for (int ks = 0; ks < 4; ++ks) {
            uint32_t af[4][4], bf[2][4];
#pragma unroll
            for (int i = 0; i < 4; ++i)
                ldm_x4(sb + aoff[i] + ks * 32, af[i][0], af[i][1], af[i][2], af[i][3]);
#pragma unroll
            for (int jp = 0; jp < 2; ++jp)
                ldm_x4(sb + boff[jp] + ks * 32, bf[jp][0], bf[jp][1], bf[jp][2], bf[jp][3]);
#pragma unroll
            for (int i = 0; i < 4; ++i)
#pragma unroll
                for (int j = 0; j < 4; ++j) {
                    const int jp = j >> 1, od = j & 1;
                    mma_bf16(acc[i][j], af[i], bf[jp][od], bf[jp][od + 2]);
                }
        }
        __syncthreads();                     // all done reading buf before reuse
        buf ^= 1;
    }

    // epilogue
    const int gr  = lane >> 2;
    const int gc2 = (lane & 3) * 2;
#pragma unroll
    for (int i = 0; i < 4; ++i) {
        const int row = m0 + wm * 64 + i * 16 + gr;
#pragma unroll
        for (int j = 0; j < 4; ++j) {
            const int col = n0 + wn * 32 + j * 8 + gc2;
            *(float2*)(C + (size_t)row * N + col) =
                make_float2(acc[i][j][0], acc[i][j][1]);
            *(float2*)(C + (size_t)(row + 8) * N + col) =
                make_float2(acc[i][j][2], acc[i][j][3]);
        }
    }
}

// ---------------------------------------------------------------------------
// Flash attention v2, fp32, causal (unchanged; ~640us)
// ---------------------------------------------------------------------------
__global__ __launch_bounds__(256, 2)
void attn_fp32(const float* __restrict__ qkv, float* __restrict__ out)
{
    extern __shared__ float sm[];
    float* Qt  = sm;
    float* Kt  = Qt + 64 * QSTR;
    float* Vs  = Kt + 64 * KSTR;
    float* Ss  = Vs + 64 * KSTR;
    float* cor = Ss + QB * KSTR;
    float* liv = cor + QB;

    const int tid = threadIdx.x;
    const int qb  = (int)gridDim.x - 1 - (int)blockIdx.x;
    const int h   = blockIdx.y;
    const int b   = blockIdx.z;

    const int ty = tid >> 4;
    const int tx = tid & 15;
    const int q0 = ty * 8;
    const int x4 = tx * 4;
    const int row2 = tid >> 1;
    const int ch   = (tid & 1) * 32;

    const float* base = qkv + (size_t)b * LL * 3 * EE + (size_t)h * DD;

    {
        const int r  = tid >> 1;
        const int c0 = (tid & 1) * 32;
        const float* qrow = base + (size_t)(qb * QB + r) * (3 * EE) + c0;
#pragma unroll
        for (int j = 0; j < 32; j += 4) {
            float4 v = *(const float4*)(qrow + j);
            Qt[(c0 + j + 0) * QSTR + r] = v.x * 0.125f;
            Qt[(c0 + j + 1) * QSTR + r] = v.y * 0.125f;
            Qt[(c0 + j + 2) * QSTR + r] = v.z * 0.125f;
            Qt[(c0 + j + 3) * QSTR + r] = v.w * 0.125f;
        }
    }

    float m_i = -1e30f, l_i = 0.f;
    float O[8][4];
#pragma unroll
    for (int i = 0; i < 8; i++)
#pragma unroll
        for (int j = 0; j < 4; j++) O[i][j] = 0.f;

    const int nkb = 2 * qb + 2;
    for (int kb = 0; kb < nkb; kb++) {
        __syncthreads();
        {
            const int r  = tid >> 2;
            const int c0 = (tid & 3) * 16;
            const float* krow = base + (size_t)(kb * KVB + r) * (3 * EE) + EE + c0;
#pragma unroll
            for (int j = 0; j < 16; j += 4) {
                float4 v = *(const float4*)(krow + j);
                Kt[(c0 + j + 0) * KSTR + r] = v.x;
                Kt[(c0 + j + 1) * KSTR + r] = v.y;
                Kt[(c0 + j + 2) * KSTR + r] = v.z;
                Kt[(c0 + j + 3) * KSTR + r] = v.w;
            }
            const float* vrow = base + (size_t)(kb * KVB + r) * (3 * EE) + 2 * EE + c0;
#pragma unroll
            for (int j = 0; j < 16; j += 4)
                *(float4*)&Vs[r * KSTR + c0 + j] = *(const float4*)(vrow + j);
        }
        __syncthreads();

        float s[8][4];
#pragma unroll
        for (int i = 0; i < 8; i++)
#pragma unroll
            for (int j = 0; j < 4; j++) s[i][j] = 0.f;

#pragma unroll 8
        for (int d = 0; d < DD; d++) {
            float a[8], bb[4];
            *(float4*)&a[0]  = *(const float4*)&Qt[d * QSTR + q0];
            *(float4*)&a[4]  = *(const float4*)&Qt[d * QSTR + q0 + 4];
            *(float4*)&bb[0] = *(const float4*)&Kt[d * KSTR + x4];
#pragma unroll
            for (int i = 0; i < 8; i++)
#pragma unroll
                for (int j = 0; j < 4; j++)
                    s[i][j] += a[i] * bb[j];
        }
#pragma unroll
        for (int i = 0; i < 8; i++)
            *(float4*)&Ss[(q0 + i) * KSTR + x4] =
                make_float4(s[i][0], s[i][1], s[i][2], s[i][3]);
        __syncthreads();

        {
            float p[32];
#pragma unroll
            for (int j = 0; j < 32; j += 4) {
                float4 v = *(const float4*)&Ss[row2 * KSTR + ch + j];
                p[j] = v.x; p[j + 1] = v.y; p[j + 2] = v.z; p[j + 3] = v.w;
            }
            if (kb >= 2 * qb) {
                const int gq  = qb * QB + row2;
                const int k0g = kb * KVB + ch;
#pragma unroll
                for (int j = 0; j < 32; j++)
                    if (k0g + j > gq) p[j] = -1e30f;
            }
            float mloc = p[0];
#pragma unroll
            for (int j = 1; j < 32; j++) mloc = fmaxf(mloc, p[j]);
            mloc = fmaxf(mloc, __shfl_xor_sync(0xffffffffu, mloc, 1));
            const float m_new = fmaxf(m_i, mloc);
            const float c     = __expf(m_i - m_new);
            float ls = 0.f;
#pragma unroll
            for (int j = 0; j < 32; j++) { p[j] = __expf(p[j] - m_new); ls += p[j]; }
            ls += __shfl_xor_sync(0xffffffffu, ls, 1);
            l_i = l_i * c + ls;
            m_i = m_new;
            if ((tid & 1) == 0) cor[row2] = c;
#pragma unroll
            for (int j = 0; j < 32; j += 4)
                *(float4*)&Ss[row2 * KSTR + ch + j] =
                    make_float4(p[j], p[j + 1], p[j + 2], p[j + 3]);
        }
        __syncthreads();

#pragma unroll
        for (int i = 0; i < 8; i++) {
            const float c = cor[q0 + i];
            O[i][0] *= c; O[i][1] *= c; O[i][2] *= c; O[i][3] *= c;
        }
#pragma unroll 2
        for (int k4 = 0; k4 < KVB; k4 += 4) {
            float4 v0 = *(const float4*)&Vs[(k4 + 0) * KSTR + x4];
            float4 v1 = *(const float4*)&Vs[(k4 + 1) * KSTR + x4];
            float4 v2 = *(const float4*)&Vs[(k4 + 2) * KSTR + x4];
            float4 v3 = *(const float4*)&Vs[(k4 + 3) * KSTR + x4];
#pragma unroll
            for (int half = 0; half < 2; half++) {
#pragma unroll
                for (int i = 0; i < 4; i++) {
                    const int r = half * 4 + i;
                    float4 pv = *(const float4*)&Ss[(q0 + r) * KSTR + k4];
                    O[r][0] = fmaf(pv.x, v0.x, O[r][0]);
                    O[r][1] = fmaf(pv.x, v0.y, O[r][1]);
                    O[r][2] = fmaf(pv.x, v0.z, O[r][2]);
                    O[r][3] = fmaf(pv.x, v0.w, O[r][3]);
                    O[r][0] = fmaf(pv.y, v1.x, O[r][0]);
                    O[r][1] = fmaf(pv.y, v1.y, O[r][1]);
                    O[r][2] = fmaf(pv.y, v1.z, O[r][2]);
                    O[r][3] = fmaf(pv.y, v1.w, O[r][3]);
                    O[r][0] = fmaf(pv.z, v2.x, O[r][0]);
                    O[r][1] = fmaf(pv.z, v2.y, O[r][1]);
                    O[r][2] = fmaf(pv.z, v2.z, O[r][2]);
                    O[r][3] = fmaf(pv.z, v2.w, O[r][3]);
                    O[r][0] = fmaf(pv.w, v3.x, O[r][0]);
                    O[r][1] = fmaf(pv.w, v3.y, O[r][1]);
                    O[r][2] = fmaf(pv.w, v3.z, O[r][2]);
                    O[r][3] = fmaf(pv.w, v3.w, O[r][3]);
                }
            }
        }
    }

    if ((tid & 1) == 0) liv[row2] = 1.f / l_i;
    __syncthreads();
#pragma unroll
    for (int i = 0; i < 8; i++) {
        const float inv = liv[q0 + i];
        float* orow = out + (size_t)(b * LL + qb * QB + q0 + i) * EE + h * DD + x4;
        *(float4*)orow = make_float4(O[i][0] * inv, O[i][1] * inv,
                                     O[i][2] * inv, O[i][3] * inv);
    }
}

// ---------------------------------------------------------------------------
extern "C" void kernel_launch(void* const* d_in, const int* in_sizes, int n_in,
                              void* d_out, int out_size)
{
    (void)in_sizes; (void)n_in; (void)out_size;
    const float* net_in = (const float*)d_in[0];   // (B,L,E)
    const float* W_qkv  = (const float*)d_in[1];   // (3E,E)
    const float* W_out  = (const float*)d_in[2];   // (E,E)
    float* outp = (float*)d_out;                   // (B,L,E)

    float *qkv_p, *att_p;
    __nv_bfloat16 *xhi, *xlo, *wqhi, *wqlo, *wohi, *wolo, *ahi, *alo;
    cudaGetSymbolAddress((void**)&qkv_p, g_qkv);
    cudaGetSymbolAddress((void**)&att_p, g_att);
    cudaGetSymbolAddress((void**)&xhi,  g_xhi);
    cudaGetSymbolAddress((void**)&xlo,  g_xlo);
    cudaGetSymbolAddress((void**)&wqhi, g_wqhi);
    cudaGetSymbolAddress((void**)&wqlo, g_wqlo);
    cudaGetSymbolAddress((void**)&wohi, g_wohi);
    cudaGetSymbolAddress((void**)&wolo, g_wolo);
    cudaGetSymbolAddress((void**)&ahi,  g_ahi);
    cudaGetSymbolAddress((void**)&alo,  g_alo);

    cudaFuncSetAttribute(gemm3x,
                         cudaFuncAttributeMaxDynamicSharedMemorySize, GSMEM);
    const int attn_smem = (64 * QSTR + 2 * 64 * KSTR + QB * KSTR + 2 * QB)
                          * (int)sizeof(float);    // 104448 B
    cudaFuncSetAttribute(attn_fp32,
                         cudaFuncAttributeMaxDynamicSharedMemorySize, attn_smem);

    // 0) fp32 -> bf16 hi/lo splits
    {
        int n4 = (MM * EE) / 4;
        split_fp32<<<(n4 + 255) / 256, 256>>>(net_in, xhi, xlo, n4);
        n4 = (3 * EE * EE) / 4;
        split_fp32<<<(n4 + 255) / 256, 256>>>(W_qkv, wqhi, wqlo, n4);
        n4 = (EE * EE) / 4;
        split_fp32<<<(n4 + 255) / 256, 256>>>(W_out, wohi, wolo, n4);
    }

    // 1) QKV projection on tensor cores: (B*L, 3E)
    dim3 g1((3 * EE) / 128, MM / 128);
    gemm3x<<<g1, 256, GSMEM>>>(xhi, xlo, wqhi, wqlo, qkv_p, 3 * EE);

    // 2) Causal flash attention -> g_att
    dim3 ga(LL / QB, HH, BB);
    attn_fp32<<<ga, 256, attn_smem>>>(qkv_p, att_p);

    // 3) split attention output, then output projection on tensor cores
    {
        int n4 = (MM * EE) / 4;
        split_fp32<<<(n4 + 255) / 256, 256>>>(att_p, ahi, alo, n4);
    }
    dim3 g3(EE / 128, MM / 128);
    gemm3x<<<g3, 256, GSMEM>>>(ahi, alo, wohi, wolo, outp, EE);
}

// round 11
// speedup vs baseline: 3.0055x; 1.5235x over previous
#include <cuda_runtime.h>
#include <cuda_bf16.h>
#include <cstdint>

// Problem constants
#define BB   2
#define LL   2048
#define HH   16
#define DD   64
#define EE   1024
#define MM   (BB * LL)      /* 4096 rows */
#define QB   128
#define KVB  64

// GEMM smem geometry: K-chunk = 64 bf16 = 128 B/row, padded to 144 B
#define GROWB   144
#define GTILEB  (128 * GROWB)          /* 18432 B per operand tile */
#define GBUFB   (2 * GTILEB)           /* A+B one stage = 36864 */
#define GSMEM   (3 * GBUFB)            /* 3-stage = 110592 B */

// Attention smem geometry
#define APITCH  144
#define AKTILE  (64 * APITCH)          /* 9216 B  (one 64-row bf16 tile) */
#define ASTAGE  (4 * AKTILE)           /* Khi,Klo,Vhi,Vlo = 36864 */
#define AQBYTES (2 * 128 * APITCH)     /* Qhi+Qlo = 36864 */
#define ASMEM   (AQBYTES + 2 * ASTAGE) /* 110592 B */

// ---------------------------------------------------------------------------
// Scratch (device globals — no runtime allocation allowed)
// ---------------------------------------------------------------------------
__device__ __nv_bfloat16 g_xhi[(size_t)MM * EE];
__device__ __nv_bfloat16 g_xlo[(size_t)MM * EE];
__device__ __nv_bfloat16 g_wqhi[(size_t)3 * EE * EE];
__device__ __nv_bfloat16 g_wqlo[(size_t)3 * EE * EE];
__device__ __nv_bfloat16 g_wohi[(size_t)EE * EE];
__device__ __nv_bfloat16 g_wolo[(size_t)EE * EE];
__device__ __nv_bfloat16 g_qkvhi[(size_t)MM * 3 * EE];
__device__ __nv_bfloat16 g_qkvlo[(size_t)MM * 3 * EE];
__device__ __nv_bfloat16 g_ahi[(size_t)MM * EE];
__device__ __nv_bfloat16 g_alo[(size_t)MM * EE];

// ---------------------------------------------------------------------------
// PTX helpers (baseline ISA only)
// ---------------------------------------------------------------------------
__device__ __forceinline__ uint32_t smem_u32(const void* p) {
    uint32_t a;
    asm("{ .reg .u64 t; cvta.to.shared.u64 t, %1; cvt.u32.u64 %0, t; }"
        : "=r"(a) : "l"(p));
    return a;
}
__device__ __forceinline__ void cp16(uint32_t saddr, const void* gaddr) {
    asm volatile("cp.async.cg.shared.global [%0], [%1], 16;"
                 :: "r"(saddr), "l"(gaddr) : "memory");
}
__device__ __forceinline__ void cp_commit() {
    asm volatile("cp.async.commit_group;" ::: "memory");
}
__device__ __forceinline__ void cp_wait1() {
    asm volatile("cp.async.wait_group 1;" ::: "memory");
}
__device__ __forceinline__ void cp_wait0() {
    asm volatile("cp.async.wait_group 0;" ::: "memory");
}
__device__ __forceinline__ void ldm4(uint32_t addr, uint32_t* r) {
    asm volatile("ldmatrix.sync.aligned.m8n8.x4.shared.b16 {%0,%1,%2,%3}, [%4];"
                 : "=r"(r[0]), "=r"(r[1]), "=r"(r[2]), "=r"(r[3]) : "r"(addr));
}
__device__ __forceinline__ void ldm4t(uint32_t addr, uint32_t* r) {
    asm volatile("ldmatrix.sync.aligned.m8n8.x4.trans.shared.b16 {%0,%1,%2,%3}, [%4];"
                 : "=r"(r[0]), "=r"(r[1]), "=r"(r[2]), "=r"(r[3]) : "r"(addr));
}
__device__ __forceinline__ void mma_bf16(float* c, const uint32_t* a,
                                         uint32_t b0, uint32_t b1) {
    asm volatile(
        "mma.sync.aligned.m16n8k16.row.col.f32.bf16.bf16.f32 "
        "{%0,%1,%2,%3}, {%4,%5,%6,%7}, {%8,%9}, {%0,%1,%2,%3};"
        : "+f"(c[0]), "+f"(c[1]), "+f"(c[2]), "+f"(c[3])
        : "r"(a[0]), "r"(a[1]), "r"(a[2]), "r"(a[3]), "r"(b0), "r"(b1));
}
__device__ __forceinline__ uint32_t pack2bf(__nv_bfloat16 x, __nv_bfloat16 y) {
    return (uint32_t)__bfloat16_as_ushort(x) |
           ((uint32_t)__bfloat16_as_ushort(y) << 16);
}

// ---------------------------------------------------------------------------
// fp32 -> (hi, lo) bf16 split
// ---------------------------------------------------------------------------
__global__ void split_fp32(const float* __restrict__ x, __nv_bfloat16* __restrict__ hi,
                           __nv_bfloat16* __restrict__ lo, int n4)
{
    int i = blockIdx.x * blockDim.x + threadIdx.x;
    if (i >= n4) return;
    float4 v = ((const float4*)x)[i];
    float f[4] = {v.x, v.y, v.z, v.w};
    uint32_t hb[4], lb[4];
#pragma unroll
    for (int j = 0; j < 4; ++j) {
        __nv_bfloat16 h = __float2bfloat16(f[j]);
        float r = f[j] - __bfloat162float(h);
        __nv_bfloat16 l = __float2bfloat16(r);
        hb[j] = (uint32_t)__bfloat16_as_ushort(h);
        lb[j] = (uint32_t)__bfloat16_as_ushort(l);
    }
    ((uint2*)hi)[i] = make_uint2(hb[0] | (hb[1] << 16), hb[2] | (hb[3] << 16));
    ((uint2*)lo)[i] = make_uint2(lb[0] | (lb[1] << 16), lb[2] | (lb[3] << 16));
}

// ---------------------------------------------------------------------------
// mma.sync 3-split GEMM: C = A[M,K]*B[N,K]^T (fp32-equivalent).
// 3-stage cp.async pipeline, 1 barrier/chunk. Output either fp32 (Cf) or
// split bf16 (Chi/Clo).
// ---------------------------------------------------------------------------
__global__ __launch_bounds__(256, 2)
void gemm3x(const __nv_bfloat16* __restrict__ Ahi, const __nv_bfloat16* __restrict__ Alo,
            const __nv_bfloat16* __restrict__ Bhi, const __nv_bfloat16* __restrict__ Blo,
            float* __restrict__ Cf, __nv_bfloat16* __restrict__ Chi,
            __nv_bfloat16* __restrict__ Clo, int N)
{
    extern __shared__ __align__(16) char smraw[];
    const uint32_t sbase = smem_u32(smraw);

    const int tid  = threadIdx.x;
    const int wid  = tid >> 5;
    const int lane = tid & 31;
    const int m0   = blockIdx.y * 128;
    const int n0   = blockIdx.x * 128;

    const int lr = tid >> 1;
    const int lh = tid & 1;
    const uint32_t sArow = (uint32_t)(lr * GROWB + lh * 64);
    const uint32_t sBrow = sArow + GTILEB;
    const size_t gAoff = (size_t)(m0 + lr) * EE + lh * 32;
    const size_t gBoff = (size_t)(n0 + lr) * EE + lh * 32;

    const int wm = wid & 1;
    const int wn = wid >> 1;
    uint32_t aoff[4], boff[2];
#pragma unroll
    for (int i = 0; i < 4; ++i)
        aoff[i] = (uint32_t)((wm * 64 + i * 16 + (lane & 15)) * GROWB + (lane >> 4) * 16);
#pragma unroll
    for (int jp = 0; jp < 2; ++jp)
        boff[jp] = (uint32_t)(GTILEB + (wn * 32 + jp * 16 + (lane & 15)) * GROWB
                              + (lane >> 4) * 16);

    float acc[4][4][4];
#pragma unroll
    for (int i = 0; i < 4; ++i)
#pragma unroll
        for (int j = 0; j < 4; ++j)
#pragma unroll
            for (int v = 0; v < 4; ++v) acc[i][j][v] = 0.f;

    auto issue = [&](int c, int stage) {
        const int ph = c >> 4;
        const int k0 = (c & 15) * 64;
        const __nv_bfloat16* ga = ((ph == 1) ? Alo : Ahi) + gAoff + k0;
        const __nv_bfloat16* gb = ((ph == 2) ? Blo : Bhi) + gBoff + k0;
        const uint32_t so = sbase + (uint32_t)(stage * GBUFB);
#pragma unroll
        for (int q = 0; q < 4; ++q) {
            cp16(so + sArow + q * 16, ga + q * 8);
            cp16(so + sBrow + q * 16, gb + q * 8);
        }
        cp_commit();
    };

    issue(0, 0);
    issue(1, 1);

    int stage = 0;
    for (int c = 0; c < 48; ++c) {
        if (c + 1 < 48) cp_wait1(); else cp_wait0();
        __syncthreads();
        if (c + 2 < 48) issue(c + 2, (stage + 2) % 3);

        const uint32_t sb = sbase + (uint32_t)(stage * GBUFB);
#pragma unroll
        for (int ks = 0; ks < 4; ++ks) {
            uint32_t af[4][4], bfr[2][4];
#pragma unroll
            for (int i = 0; i < 4; ++i) ldm4(sb + aoff[i] + ks * 32, af[i]);
#pragma unroll
            for (int jp = 0; jp < 2; ++jp) ldm4(sb + boff[jp] + ks * 32, bfr[jp]);
#pragma unroll
            for (int i = 0; i < 4; ++i)
#pragma unroll
                for (int j = 0; j < 4; ++j) {
                    const int jp = j >> 1, od = j & 1;
                    mma_bf16(acc[i][j], af[i], bfr[jp][od], bfr[jp][od + 2]);
                }
        }
        stage = (stage + 1) % 3;
    }

    const int gr  = lane >> 2;
    const int gc2 = (lane & 3) * 2;
#pragma unroll
    for (int i = 0; i < 4; ++i) {
        const int row = m0 + wm * 64 + i * 16 + gr;
#pragma unroll
        for (int j = 0; j < 4; ++j) {
            const int col = n0 + wn * 32 + j * 8 + gc2;
            if (Cf) {
                *(float2*)(Cf + (size_t)row * N + col) =
                    make_float2(acc[i][j][0], acc[i][j][1]);
                *(float2*)(Cf + (size_t)(row + 8) * N + col) =
                    make_float2(acc[i][j][2], acc[i][j][3]);
            } else {
#pragma unroll
                for (int rr = 0; rr < 2; ++rr) {
                    float v0 = acc[i][j][rr * 2], v1 = acc[i][j][rr * 2 + 1];
                    __nv_bfloat16 h0 = __float2bfloat16(v0);
                    __nv_bfloat16 h1 = __float2bfloat16(v1);
                    __nv_bfloat16 l0 = __float2bfloat16(v0 - __bfloat162float(h0));
                    __nv_bfloat16 l1 = __float2bfloat16(v1 - __bfloat162float(h1));
                    const size_t off = (size_t)(row + rr * 8) * N + col;
                    *(uint32_t*)(Chi + off) = pack2bf(h0, h1);
                    *(uint32_t*)(Clo + off) = pack2bf(l0, l1);
                }
            }
        }
    }
}

// ---------------------------------------------------------------------------
// Tensor-core flash attention, causal, bf16 3-split.
// CTA = 128 queries x one (b,h), 8 warps x 16 rows. Per-warp S/softmax/P/O all
// register-resident (m16n8 accumulator layout). K/V double-buffered cp.async.
// ---------------------------------------------------------------------------
__global__ __launch_bounds__(256, 2)
void attn_tc(const __nv_bfloat16* __restrict__ qkvh,
             const __nv_bfloat16* __restrict__ qkvl,
             __nv_bfloat16* __restrict__ ahi, __nv_bfloat16* __restrict__ alo)
{
    extern __shared__ __align__(16) char smA[];
    const uint32_t sQ  = smem_u32(smA);
    const uint32_t sKV = sQ + AQBYTES;

    const int tid  = threadIdx.x;
    const int wid  = tid >> 5;
    const int lane = tid & 31;
    const int qb   = (int)gridDim.x - 1 - (int)blockIdx.x;
    const int h    = blockIdx.y;
    const int b    = blockIdx.z;

    const size_t rowQ0 = (size_t)(b * LL + qb * QB);
    const size_t rowB  = (size_t)(b * LL);

    // Q: 2048 cp16 slots (hi+lo)
#pragma unroll
    for (int i = 0; i < 8; ++i) {
        int s = tid + (i << 8);
        int half = s >> 10;
        int row  = (s >> 3) & 127;
        int u    = s & 7;
        const __nv_bfloat16* src = (half ? qkvl : qkvh)
            + (rowQ0 + row) * (3 * EE) + h * DD + u * 8;
        cp16(sQ + half * 18432 + row * APITCH + u * 16, src);
    }
    auto issue_kv = [&](int kb, uint32_t dst) {
#pragma unroll
        for (int i = 0; i < 8; ++i) {
            int s = tid + (i << 8);
            int tn  = s >> 9;              // 0 Khi 1 Klo 2 Vhi 3 Vlo
            int row = (s >> 3) & 63;
            int u   = s & 7;
            const __nv_bfloat16* base = (tn & 1) ? qkvl : qkvh;
            int col = ((tn >> 1) ? 2 * EE : EE) + h * DD + u * 8;
            cp16(dst + tn * AKTILE + row * APITCH + u * 16,
                 base + (rowB + (size_t)kb * KVB + row) * (3 * EE) + col);
        }
    };
    issue_kv(0, sKV);
    cp_commit();
    cp_wait0();
    __syncthreads();

    const int q0   = wid * 16;
    const int qmin = qb * QB + q0;
    const int rA = lane & 15, uA = (lane >> 4);                 // non-trans
    const int rT = (lane & 7) + ((lane >> 4) << 3);             // trans row
    const int uT = (lane >> 3) & 1;                             // trans unit

    float m0 = -1e30f, m1 = -1e30f, l0 = 0.f, l1 = 0.f;
    float O[8][4];
#pragma unroll
    for (int j = 0; j < 8; ++j)
#pragma unroll
        for (int v = 0; v < 4; ++v) O[j][v] = 0.f;

    const int nkb = 2 * qb + 2;
    int buf = 0;
    for (int kb = 0; kb < nkb; ++kb) {
        if (kb + 1 < nkb) { issue_kv(kb + 1, sKV + (buf ^ 1) * ASTAGE); cp_commit(); }
        const uint32_t st = sKV + buf * ASTAGE;
        const bool skip = (kb * KVB > qmin + 15);
        if (!skip) {
            float acc[8][4];
#pragma unroll
            for (int j = 0; j < 8; ++j)
#pragma unroll
                for (int v = 0; v < 4; ++v) acc[j][v] = 0.f;

            // ---- S = Q K^T (3-split) ----
#pragma unroll
            for (int ks = 0; ks < 4; ++ks) {
                uint32_t aH[4], aL[4];
                ldm4(sQ + (q0 + rA) * APITCH + uA * 16 + ks * 32, aH);
                ldm4(sQ + 18432 + (q0 + rA) * APITCH + uA * 16 + ks * 32, aL);
#pragma unroll
                for (int jp = 0; jp < 4; ++jp) {
                    uint32_t bH[4], bL[4];
                    const uint32_t ko = (uint32_t)((jp * 16 + rA) * APITCH + uA * 16 + ks * 32);
                    ldm4(st + ko, bH);
                    mma_bf16(acc[2 * jp],     aH, bH[0], bH[2]);
                    mma_bf16(acc[2 * jp + 1], aH, bH[1], bH[3]);
                    mma_bf16(acc[2 * jp],     aL, bH[0], bH[2]);
                    mma_bf16(acc[2 * jp + 1], aL, bH[1], bH[3]);
                    ldm4(st + AKTILE + ko, bL);
                    mma_bf16(acc[2 * jp],     aH, bL[0], bL[2]);
                    mma_bf16(acc[2 * jp + 1], aH, bL[1], bL[3]);
                }
            }

            // ---- scale + causal mask ----
            const int r0 = qmin + (lane >> 2), r1 = r0 + 8;
            const bool needmask = (kb * KVB + KVB - 1 > qmin);
#pragma unroll
            for (int j = 0; j < 8; ++j) {
                acc[j][0] *= 0.125f; acc[j][1] *= 0.125f;
                acc[j][2] *= 0.125f; acc[j][3] *= 0.125f;
                if (needmask) {
                    const int key = kb * KVB + j * 8 + ((lane & 3) << 1);
                    if (key     > r0) acc[j][0] = -1e30f;
                    if (key + 1 > r0) acc[j][1] = -1e30f;
                    if (key     > r1) acc[j][2] = -1e30f;
                    if (key + 1 > r1) acc[j][3] = -1e30f;
                }
            }

            // ---- online softmax (rows r0, r1; 4-lane groups) ----
            float mx0 = -1e30f, mx1 = -1e30f;
#pragma unroll
            for (int j = 0; j < 8; ++j) {
                mx0 = fmaxf(mx0, fmaxf(acc[j][0], acc[j][1]));
                mx1 = fmaxf(mx1, fmaxf(acc[j][2], acc[j][3]));
            }
            mx0 = fmaxf(mx0, __shfl_xor_sync(0xffffffffu, mx0, 1));
            mx0 = fmaxf(mx0, __shfl_xor_sync(0xffffffffu, mx0, 2));
            mx1 = fmaxf(mx1, __shfl_xor_sync(0xffffffffu, mx1, 1));
            mx1 = fmaxf(mx1, __shfl_xor_sync(0xffffffffu, mx1, 2));
            const float mn0 = fmaxf(m0, mx0), mn1 = fmaxf(m1, mx1);
            const float c0 = __expf(m0 - mn0), c1 = __expf(m1 - mn1);
            float s0 = 0.f, s1 = 0.f;
#pragma unroll
            for (int j = 0; j < 8; ++j) {
                acc[j][0] = __expf(acc[j][0] - mn0); s0 += acc[j][0];
                acc[j][1] = __expf(acc[j][1] - mn0); s0 += acc[j][1];
                acc[j][2] = __expf(acc[j][2] - mn1); s1 += acc[j][2];
                acc[j][3] = __expf(acc[j][3] - mn1); s1 += acc[j][3];
            }
            s0 += __shfl_xor_sync(0xffffffffu, s0, 1);
            s0 += __shfl_xor_sync(0xffffffffu, s0, 2);
            s1 += __shfl_xor_sync(0xffffffffu, s1, 1);
            s1 += __shfl_xor_sync(0xffffffffu, s1, 2);
            l0 = l0 * c0 + s0; l1 = l1 * c1 + s1;
            m0 = mn0; m1 = mn1;
#pragma unroll
            for (int j = 0; j < 8; ++j) {
                O[j][0] *= c0; O[j][1] *= c0;
                O[j][2] *= c1; O[j][3] *= c1;
            }

            // ---- O += P V (3-split); P frags straight from accumulators ----
#pragma unroll
            for (int t = 0; t < 4; ++t) {
                uint32_t aPh[4], aPl[4];
#pragma unroll
                for (int hf = 0; hf < 2; ++hf) {
                    const float* pv = acc[2 * t + hf];
                    __nv_bfloat16 h0 = __float2bfloat16(pv[0]);
                    __nv_bfloat16 h1 = __float2bfloat16(pv[1]);
                    __nv_bfloat16 h2 = __float2bfloat16(pv[2]);
                    __nv_bfloat16 h3 = __float2bfloat16(pv[3]);
                    aPh[hf * 2]     = pack2bf(h0, h1);
                    aPh[hf * 2 + 1] = pack2bf(h2, h3);
                    aPl[hf * 2]     = pack2bf(
                        __float2bfloat16(pv[0] - __bfloat162float(h0)),
                        __float2bfloat16(pv[1] - __bfloat162float(h1)));
                    aPl[hf * 2 + 1] = pack2bf(
                        __float2bfloat16(pv[2] - __bfloat162float(h2)),
                        __float2bfloat16(pv[3] - __bfloat162float(h3)));
                }
#pragma unroll
                for (int jp = 0; jp < 4; ++jp) {
                    uint32_t vH[4], vL[4];
                    const uint32_t vo = (uint32_t)((t * 16 + rT) * APITCH
                                                   + (jp * 2 + uT) * 16);
                    ldm4t(st + 2 * AKTILE + vo, vH);
                    mma_bf16(O[2 * jp],     aPh, vH[0], vH[2]);
                    mma_bf16(O[2 * jp + 1], aPh, vH[1], vH[3]);
                    mma_bf16(O[2 * jp],     aPl, vH[0], vH[2]);
                    mma_bf16(O[2 * jp + 1], aPl, vH[1], vH[3]);
                    ldm4t(st + 3 * AKTILE + vo, vL);
                    mma_bf16(O[2 * jp],     aPh, vL[0], vL[2]);
                    mma_bf16(O[2 * jp + 1], aPh, vL[1], vL[3]);
                }
            }
        }
        if (kb + 1 < nkb) cp_wait0();
        __syncthreads();
        buf ^= 1;
    }

    // ---- epilogue: normalize + split-bf16 store ----
    const float i0 = 1.f / l0, i1 = 1.f / l1;
    const size_t g0 = (rowQ0 + q0 + (lane >> 2)) * EE + h * DD;
    const size_t g1 = g0 + (size_t)8 * EE;
#pragma unroll
    for (int j = 0; j < 8; ++j) {
        const int col = j * 8 + ((lane & 3) << 1);
#pragma unroll
        for (int rr = 0; rr < 2; ++rr) {
            const float v0 = O[j][rr * 2] * (rr ? i1 : i0);
            const float v1 = O[j][rr * 2 + 1] * (rr ? i1 : i0);
            __nv_bfloat16 h0 = __float2bfloat16(v0);
            __nv_bfloat16 h1 = __float2bfloat16(v1);
            __nv_bfloat16 lo0 = __float2bfloat16(v0 - __bfloat162float(h0));
            __nv_bfloat16 lo1 = __float2bfloat16(v1 - __bfloat162float(h1));
            const size_t off = (rr ? g1 : g0) + col;
            *(uint32_t*)(ahi + off) = pack2bf(h0, h1);
            *(uint32_t*)(alo + off) = pack2bf(lo0, lo1);
        }
    }
}

// ---------------------------------------------------------------------------
extern "C" void kernel_launch(void* const* d_in, const int* in_sizes, int n_in,
                              void* d_out, int out_size)
{
    (void)in_sizes; (void)n_in; (void)out_size;
    const float* net_in = (const float*)d_in[0];
    const float* W_qkv  = (const float*)d_in[1];
    const float* W_out  = (const float*)d_in[2];
    float* outp = (float*)d_out;

    __nv_bfloat16 *xhi, *xlo, *wqhi, *wqlo, *wohi, *wolo, *qh, *ql, *ahi, *alo;
    cudaGetSymbolAddress((void**)&xhi,  g_xhi);
    cudaGetSymbolAddress((void**)&xlo,  g_xlo);
    cudaGetSymbolAddress((void**)&wqhi, g_wqhi);
    cudaGetSymbolAddress((void**)&wqlo, g_wqlo);
    cudaGetSymbolAddress((void**)&wohi, g_wohi);
    cudaGetSymbolAddress((void**)&wolo, g_wolo);
    cudaGetSymbolAddress((void**)&qh,   g_qkvhi);
    cudaGetSymbolAddress((void**)&ql,   g_qkvlo);
    cudaGetSymbolAddress((void**)&ahi,  g_ahi);
    cudaGetSymbolAddress((void**)&alo,  g_alo);

    cudaFuncSetAttribute(gemm3x,
                         cudaFuncAttributeMaxDynamicSharedMemorySize, GSMEM);
    cudaFuncSetAttribute(attn_tc,
                         cudaFuncAttributeMaxDynamicSharedMemorySize, ASMEM);

    // 0) input/weight splits
    {
        int n4 = (MM * EE) / 4;
        split_fp32<<<(n4 + 255) / 256, 256>>>(net_in, xhi, xlo, n4);
        n4 = (3 * EE * EE) / 4;
        split_fp32<<<(n4 + 255) / 256, 256>>>(W_qkv, wqhi, wqlo, n4);
        n4 = (EE * EE) / 4;
        split_fp32<<<(n4 + 255) / 256, 256>>>(W_out, wohi, wolo, n4);
    }

    // 1) QKV projection -> split-bf16 qkv
    dim3 g1((3 * EE) / 128, MM / 128);
    gemm3x<<<g1, 256, GSMEM>>>(xhi, xlo, wqhi, wqlo, nullptr, qh, ql, 3 * EE);

    // 2) Tensor-core causal flash attention -> split-bf16 activations
    dim3 ga(LL / QB, HH, BB);
    attn_tc<<<ga, 256, ASMEM>>>(qh, ql, ahi, alo);

    // 3) Output projection -> fp32 d_out
    dim3 g3(EE / 128, MM / 128);
    gemm3x<<<g3, 256, GSMEM>>>(ahi, alo, wohi, wolo, outp, nullptr, nullptr, EE);
}